// round 1
// baseline (speedup 1.0000x reference)
#include <cuda_runtime.h>
#include <math.h>

#define EMB   384
#define HEADS 6
#define QD    64
#define DFF   1536
#define BB    32
#define TT    512
#define ROWS  (BB*TT)   // 16384

// ---------------- scratch (device globals; no allocation allowed) ----------------
__device__ float g_h [ROWS*EMB];   // ln1 output
__device__ float g_q [ROWS*EMB];   // [B,H,T,D]
__device__ float g_k [ROWS*EMB];
__device__ float g_v [ROWS*EMB];
__device__ float g_o [ROWS*EMB];   // attention output, [B,T,C] layout
__device__ float g_h2[ROWS*EMB];   // ln2 output
__device__ float g_ff[ROWS*DFF];   // relu(h2@W1+b)

// ---------------- LayerNorm: one block per row, 128 threads ----------------
__global__ void ln_kernel(const float* __restrict__ x,
                          const float* __restrict__ g,
                          const float* __restrict__ b,
                          float* __restrict__ out) {
    __shared__ float red[4];
    int row = blockIdx.x;
    int tid = threadIdx.x;
    const float* xr = x + (size_t)row * EMB;

    float v0 = xr[tid], v1 = xr[tid + 128], v2 = xr[tid + 256];
    float s = v0 + v1 + v2;
    #pragma unroll
    for (int o = 16; o; o >>= 1) s += __shfl_xor_sync(0xffffffffu, s, o);
    if ((tid & 31) == 0) red[tid >> 5] = s;
    __syncthreads();
    float mu = (red[0] + red[1] + red[2] + red[3]) * (1.0f / EMB);
    __syncthreads();

    float d0 = v0 - mu, d1 = v1 - mu, d2 = v2 - mu;
    float vv = d0*d0 + d1*d1 + d2*d2;
    #pragma unroll
    for (int o = 16; o; o >>= 1) vv += __shfl_xor_sync(0xffffffffu, vv, o);
    if ((tid & 31) == 0) red[tid >> 5] = vv;
    __syncthreads();
    float var = (red[0] + red[1] + red[2] + red[3]) * (1.0f / EMB);
    float inv = rsqrtf(var + 1e-5f);

    float* orow = out + (size_t)row * EMB;
    orow[tid]       = d0 * inv * g[tid]       + b[tid];
    orow[tid + 128] = d1 * inv * g[tid + 128] + b[tid + 128];
    orow[tid + 256] = d2 * inv * g[tid + 256] + b[tid + 256];
}

// ---------------- generic fp32 GEMM: C[M,N] = A[M,K] @ W[K,N] (+epilogue) ----------------
// BM=BN=64, BK=16, 256 threads, each thread 4x4 outputs.
// EPI: 0 = scatter to [B,H,T,D] (QKV), 1 = +bias +residual, 2 = +bias +relu
template<int EPI>
__global__ void __launch_bounds__(256)
gemm_kernel(const float* __restrict__ A, const float* __restrict__ W,
            const float* __restrict__ bias, const float* __restrict__ R,
            float* __restrict__ C, int M, int N, int K) {
    __shared__ float As[16][64];     // transposed: As[k][m]
    __shared__ float Bs[16][64];

    int tid = threadIdx.x;
    int n0 = blockIdx.x * 64;
    int m0 = blockIdx.y * 64;
    int tr = tid >> 4;               // 0..15
    int tc = tid & 15;               // 0..15

    float acc[4][4];
    #pragma unroll
    for (int i = 0; i < 4; i++)
        #pragma unroll
        for (int j = 0; j < 4; j++) acc[i][j] = 0.f;

    int arow = tid >> 2, ac4 = tid & 3;   // A loader: 64 rows x 4 float4
    int brow = tid >> 4, bc4 = tid & 15;  // B loader: 16 rows x 16 float4

    for (int k0 = 0; k0 < K; k0 += 16) {
        float4 av = *(const float4*)&A[(size_t)(m0 + arow) * K + k0 + ac4 * 4];
        As[ac4*4 + 0][arow] = av.x;
        As[ac4*4 + 1][arow] = av.y;
        As[ac4*4 + 2][arow] = av.z;
        As[ac4*4 + 3][arow] = av.w;
        *(float4*)&Bs[brow][bc4 * 4] =
            *(const float4*)&W[(size_t)(k0 + brow) * N + n0 + bc4 * 4];
        __syncthreads();

        #pragma unroll
        for (int kk = 0; kk < 16; kk++) {
            float4 a4 = *(float4*)&As[kk][tr * 4];
            float4 b4 = *(float4*)&Bs[kk][tc * 4];
            float ar[4] = {a4.x, a4.y, a4.z, a4.w};
            float br[4] = {b4.x, b4.y, b4.z, b4.w};
            #pragma unroll
            for (int i = 0; i < 4; i++)
                #pragma unroll
                for (int j = 0; j < 4; j++)
                    acc[i][j] += ar[i] * br[j];
        }
        __syncthreads();
    }

    #pragma unroll
    for (int i = 0; i < 4; i++) {
        int m = m0 + tr * 4 + i;
        #pragma unroll
        for (int j = 0; j < 4; j++) {
            int n = n0 + tc * 4 + j;
            float val = acc[i][j];
            if (EPI == 0) {
                // scatter [row=b*T+t, col=head*64+d] -> [((b*H+head)*T+t)*64+d]
                int b_ = m / TT, t_ = m % TT;
                int head = n >> 6, d = n & 63;
                C[(((size_t)(b_ * HEADS + head)) * TT + t_) * 64 + d] = val;
            } else if (EPI == 1) {
                C[(size_t)m * N + n] = val + bias[n] + R[(size_t)m * N + n];
            } else {
                val += bias[n];
                C[(size_t)m * N + n] = val > 0.f ? val : 0.f;
            }
        }
    }
}

// ---------------- flash attention: block = (q-tile of 128, b*h), 128 threads ----------------
// dynamic smem: Ks[64*64] + Vs[64*64] + Ss[128*65]
#define ATTN_SMEM ((64*64 + 64*64 + 128*65) * sizeof(float))

__global__ void __launch_bounds__(128)
attn_kernel(const float* __restrict__ q, const float* __restrict__ k,
            const float* __restrict__ v, float* __restrict__ o) {
    extern __shared__ float sm[];
    float* Ks = sm;            // [64][64]
    float* Vs = sm + 4096;     // [64][64]
    float* Ss = sm + 8192;     // [128][65]

    int bh = blockIdx.y;
    int q0 = blockIdx.x * 128;
    int r  = threadIdx.x;      // query row within tile
    int qg = q0 + r;           // global query index

    const float* qb = q + ((size_t)bh * TT + qg) * 64;
    float qreg[64];
    #pragma unroll
    for (int d = 0; d < 64; d++) qreg[d] = qb[d] * 0.125f;  // 1/sqrt(64)

    float acc[64];
    #pragma unroll
    for (int d = 0; d < 64; d++) acc[d] = 0.f;
    float mrun = -1e30f, lrun = 0.f;

    int kmax = q0 + 128;   // causal upper bound (exclusive)
    for (int k0 = 0; k0 < kmax; k0 += 64) {
        const float4* kb = (const float4*)(k + ((size_t)bh * TT + k0) * 64);
        const float4* vb = (const float4*)(v + ((size_t)bh * TT + k0) * 64);
        for (int i = r; i < 1024; i += 128) {
            ((float4*)Ks)[i] = kb[i];
            ((float4*)Vs)[i] = vb[i];
        }
        __syncthreads();

        // phase A: scores
        float mx = -1e30f;
        for (int j = 0; j < 64; j++) {
            float s = 0.f;
            const float* kr = Ks + j * 64;
            #pragma unroll
            for (int d = 0; d < 64; d++) s += qreg[d] * kr[d];
            if (k0 + j > qg) s = -1e30f;
            Ss[r * 65 + j] = s;
            mx = fmaxf(mx, s);
        }

        // phase B: online softmax + PV
        float mnew = fmaxf(mrun, mx);
        float scale = __expf(mrun - mnew);
        lrun *= scale;
        #pragma unroll
        for (int d = 0; d < 64; d++) acc[d] *= scale;
        for (int j = 0; j < 64; j++) {
            float p = __expf(Ss[r * 65 + j] - mnew);
            lrun += p;
            const float* vr = Vs + j * 64;
            #pragma unroll
            for (int d = 0; d < 64; d++) acc[d] += p * vr[d];
        }
        mrun = mnew;
        __syncthreads();
    }

    int b_ = bh / HEADS, h_ = bh % HEADS;
    float* ob = o + ((size_t)(b_ * TT + qg)) * EMB + h_ * 64;
    float inv = 1.f / lrun;
    #pragma unroll
    for (int d = 0; d < 64; d++) ob[d] = acc[d] * inv;
}

// ---------------- launch ----------------
extern "C" void kernel_launch(void* const* d_in, const int* in_sizes, int n_in,
                              void* d_out, int out_size) {
    const float* x   = (const float*)d_in[0];
    const float* Wq  = (const float*)d_in[1];
    const float* Wk  = (const float*)d_in[2];
    const float* Wv  = (const float*)d_in[3];
    const float* Wp  = (const float*)d_in[4];
    const float* bp  = (const float*)d_in[5];
    const float* g1  = (const float*)d_in[6];
    const float* b1  = (const float*)d_in[7];
    const float* g2  = (const float*)d_in[8];
    const float* b2  = (const float*)d_in[9];
    const float* W1  = (const float*)d_in[10];
    const float* bf1 = (const float*)d_in[11];
    const float* W2  = (const float*)d_in[12];
    const float* bf2 = (const float*)d_in[13];
    float* out = (float*)d_out;

    float *h, *q, *k, *v, *o, *h2, *ff;
    cudaGetSymbolAddress((void**)&h,  g_h);
    cudaGetSymbolAddress((void**)&q,  g_q);
    cudaGetSymbolAddress((void**)&k,  g_k);
    cudaGetSymbolAddress((void**)&v,  g_v);
    cudaGetSymbolAddress((void**)&o,  g_o);
    cudaGetSymbolAddress((void**)&h2, g_h2);
    cudaGetSymbolAddress((void**)&ff, g_ff);

    static bool attr_done = false;
    if (!attr_done) {
        cudaFuncSetAttribute(attn_kernel, cudaFuncAttributeMaxDynamicSharedMemorySize,
                             (int)ATTN_SMEM);
        attr_done = true;
    }

    // 1) ln1
    ln_kernel<<<ROWS, 128>>>(x, g1, b1, h);

    // 2) QKV projections with head-transposed scatter
    {
        dim3 grid(EMB / 64, ROWS / 64);
        gemm_kernel<0><<<grid, 256>>>(h, Wq, nullptr, nullptr, q, ROWS, EMB, EMB);
        gemm_kernel<0><<<grid, 256>>>(h, Wk, nullptr, nullptr, k, ROWS, EMB, EMB);
        gemm_kernel<0><<<grid, 256>>>(h, Wv, nullptr, nullptr, v, ROWS, EMB, EMB);
    }

    // 3) causal attention
    {
        dim3 grid(TT / 128, BB * HEADS);
        attn_kernel<<<grid, 128, ATTN_SMEM>>>(q, k, v, o);
    }

    // 4) out projection + residual -> d_out  (x1 = x + o@Wp + bp)
    {
        dim3 grid(EMB / 64, ROWS / 64);
        gemm_kernel<1><<<grid, 256>>>(o, Wp, bp, x, out, ROWS, EMB, EMB);
    }

    // 5) ln2 on x1
    ln_kernel<<<ROWS, 128>>>(out, g2, b2, h2);

    // 6) FF1: relu(h2@W1 + bf1)
    {
        dim3 grid(DFF / 64, ROWS / 64);
        gemm_kernel<2><<<grid, 256>>>(h2, W1, bf1, nullptr, ff, ROWS, DFF, EMB);
    }

    // 7) FF2: out = x1 + ff@W2 + bf2   (reads+writes d_out, one thread per element)
    {
        dim3 grid(EMB / 64, ROWS / 64);
        gemm_kernel<1><<<grid, 256>>>(ff, W2, bf2, out, out, ROWS, EMB, DFF);
    }
}

// round 2
// speedup vs baseline: 2.1920x; 2.1920x over previous
#include <cuda_runtime.h>
#include <math.h>
#include <stdint.h>

#define EMB   384
#define HEADS 6
#define QD    64
#define DFF   1536
#define BB    32
#define TT    512
#define ROWS  (BB*TT)   // 16384

// ---------------- scratch (device globals; no allocation allowed) ----------------
__device__ float g_h [ROWS*EMB];   // ln1 output
__device__ float g_q [ROWS*EMB];   // [B,H,T,D]
__device__ float g_k [ROWS*EMB];
__device__ float g_v [ROWS*EMB];
__device__ float g_o [ROWS*EMB];   // attention output, [B,T,C] layout
__device__ float g_h2[ROWS*EMB];   // ln2 output
__device__ float g_ff[ROWS*DFF];   // relu(h2@W1+b)

// ---------------- LayerNorm: one block per row, 128 threads ----------------
__global__ void ln_kernel(const float* __restrict__ x,
                          const float* __restrict__ g,
                          const float* __restrict__ b,
                          float* __restrict__ out) {
    __shared__ float red[4];
    int row = blockIdx.x;
    int tid = threadIdx.x;
    const float* xr = x + (size_t)row * EMB;

    float v0 = xr[tid], v1 = xr[tid + 128], v2 = xr[tid + 256];
    float s = v0 + v1 + v2;
    #pragma unroll
    for (int o = 16; o; o >>= 1) s += __shfl_xor_sync(0xffffffffu, s, o);
    if ((tid & 31) == 0) red[tid >> 5] = s;
    __syncthreads();
    float mu = (red[0] + red[1] + red[2] + red[3]) * (1.0f / EMB);
    __syncthreads();

    float d0 = v0 - mu, d1 = v1 - mu, d2 = v2 - mu;
    float vv = d0*d0 + d1*d1 + d2*d2;
    #pragma unroll
    for (int o = 16; o; o >>= 1) vv += __shfl_xor_sync(0xffffffffu, vv, o);
    if ((tid & 31) == 0) red[tid >> 5] = vv;
    __syncthreads();
    float var = (red[0] + red[1] + red[2] + red[3]) * (1.0f / EMB);
    float inv = rsqrtf(var + 1e-5f);

    float* orow = out + (size_t)row * EMB;
    orow[tid]       = d0 * inv * g[tid]       + b[tid];
    orow[tid + 128] = d1 * inv * g[tid + 128] + b[tid + 128];
    orow[tid + 256] = d2 * inv * g[tid + 256] + b[tid + 256];
}

// ---------------- TF32 tensor-core GEMM: C[M,N] = A[M,K] @ W[K,N] (+epilogue) ----
// BM=BN=128, BK=16, 256 threads (8 warps, 2x4 warp grid), warp tile 64x32.
// mma.sync.aligned.m16n8k8.row.col.f32.tf32.tf32.f32, double-buffered smem.
// A smem stride 20 words, B smem stride 136 words (both conflict-free for the
// mma fragment read patterns).
// EPI: 0 = scatter to [B,H,T,D] (QKV), 1 = +bias +residual, 2 = +bias +relu
#define A_STRIDE 20
#define B_STRIDE 136
#define A_WORDS  (128 * A_STRIDE)          // 2560
#define B_WORDS  (16  * B_STRIDE)          // 2176
#define BUF_WORDS (A_WORDS + B_WORDS)      // 4736
#define GEMM_SMEM (2 * BUF_WORDS * 4)      // 37888 bytes

__device__ __forceinline__ uint32_t f2tf32(float f) {
    uint32_t r;
    asm("cvt.rna.tf32.f32 %0, %1;" : "=r"(r) : "f"(f));
    return r;
}

template<int EPI>
__global__ void __launch_bounds__(256)
tmma_gemm(const float* __restrict__ A, const float* __restrict__ W,
          const float* __restrict__ bias, const float* __restrict__ R,
          float* __restrict__ C, int M, int N, int K) {
    extern __shared__ uint32_t smbuf[];

    int tid  = threadIdx.x;
    int lane = tid & 31;
    int warp = tid >> 5;
    int wm   = warp >> 2;        // 0..1
    int wn   = warp & 3;         // 0..3
    int l4   = lane >> 2;        // 0..7
    int qq   = lane & 3;         // 0..3
    int n0   = blockIdx.x * 128;
    int m0   = blockIdx.y * 128;

    // global loader mapping
    int ar = tid >> 2;           // 0..63  (A rows; +64 for second half)
    int ac = (tid & 3) * 4;      // 0,4,8,12 (k within tile)
    int br = tid >> 4;           // 0..15  (B k-rows)
    int bc = (tid & 15) * 4;     // 0..60  (n within tile; +64 second half)

    float4 a0v, a1v, b0v, b1v;

    float acc[4][4][4];
    #pragma unroll
    for (int mt = 0; mt < 4; mt++)
        #pragma unroll
        for (int nt = 0; nt < 4; nt++)
            #pragma unroll
            for (int e = 0; e < 4; e++) acc[mt][nt][e] = 0.f;

    // prologue: load tile 0
    {
        int k0 = 0;
        a0v = *(const float4*)&A[(size_t)(m0 + ar) * K + k0 + ac];
        a1v = *(const float4*)&A[(size_t)(m0 + ar + 64) * K + k0 + ac];
        b0v = *(const float4*)&W[(size_t)(k0 + br) * N + n0 + bc];
        b1v = *(const float4*)&W[(size_t)(k0 + br) * N + n0 + bc + 64];
        uint32_t* As = smbuf;
        uint32_t* Bs = smbuf + A_WORDS;
        uint4 t;
        t.x=f2tf32(a0v.x); t.y=f2tf32(a0v.y); t.z=f2tf32(a0v.z); t.w=f2tf32(a0v.w);
        *(uint4*)&As[ar * A_STRIDE + ac] = t;
        t.x=f2tf32(a1v.x); t.y=f2tf32(a1v.y); t.z=f2tf32(a1v.z); t.w=f2tf32(a1v.w);
        *(uint4*)&As[(ar + 64) * A_STRIDE + ac] = t;
        t.x=f2tf32(b0v.x); t.y=f2tf32(b0v.y); t.z=f2tf32(b0v.z); t.w=f2tf32(b0v.w);
        *(uint4*)&Bs[br * B_STRIDE + bc] = t;
        t.x=f2tf32(b1v.x); t.y=f2tf32(b1v.y); t.z=f2tf32(b1v.z); t.w=f2tf32(b1v.w);
        *(uint4*)&Bs[br * B_STRIDE + bc + 64] = t;
    }
    __syncthreads();

    int nsteps = K >> 4;
    int cur = 0;
    for (int s = 0; s < nsteps; s++) {
        bool more = (s + 1 < nsteps);
        if (more) {
            int k0 = (s + 1) << 4;
            a0v = *(const float4*)&A[(size_t)(m0 + ar) * K + k0 + ac];
            a1v = *(const float4*)&A[(size_t)(m0 + ar + 64) * K + k0 + ac];
            b0v = *(const float4*)&W[(size_t)(k0 + br) * N + n0 + bc];
            b1v = *(const float4*)&W[(size_t)(k0 + br) * N + n0 + bc + 64];
        }

        uint32_t* As = smbuf + cur * BUF_WORDS;
        uint32_t* Bs = smbuf + cur * BUF_WORDS + A_WORDS;

        #pragma unroll
        for (int kk = 0; kk < 2; kk++) {
            int kb = kk * 8;
            uint32_t af[4][4], bf[4][2];
            #pragma unroll
            for (int mt = 0; mt < 4; mt++) {
                int mrow = wm * 64 + mt * 16 + l4;
                af[mt][0] = As[mrow * A_STRIDE + kb + qq];
                af[mt][1] = As[(mrow + 8) * A_STRIDE + kb + qq];
                af[mt][2] = As[mrow * A_STRIDE + kb + qq + 4];
                af[mt][3] = As[(mrow + 8) * A_STRIDE + kb + qq + 4];
            }
            #pragma unroll
            for (int nt = 0; nt < 4; nt++) {
                int nc = wn * 32 + nt * 8 + l4;
                bf[nt][0] = Bs[(kb + qq) * B_STRIDE + nc];
                bf[nt][1] = Bs[(kb + qq + 4) * B_STRIDE + nc];
            }
            #pragma unroll
            for (int mt = 0; mt < 4; mt++)
                #pragma unroll
                for (int nt = 0; nt < 4; nt++)
                    asm volatile(
                        "mma.sync.aligned.m16n8k8.row.col.f32.tf32.tf32.f32 "
                        "{%0,%1,%2,%3}, {%4,%5,%6,%7}, {%8,%9}, {%0,%1,%2,%3};"
                        : "+f"(acc[mt][nt][0]), "+f"(acc[mt][nt][1]),
                          "+f"(acc[mt][nt][2]), "+f"(acc[mt][nt][3])
                        : "r"(af[mt][0]), "r"(af[mt][1]), "r"(af[mt][2]), "r"(af[mt][3]),
                          "r"(bf[nt][0]), "r"(bf[nt][1]));
        }

        if (more) {
            uint32_t* Ad = smbuf + (cur ^ 1) * BUF_WORDS;
            uint32_t* Bd = smbuf + (cur ^ 1) * BUF_WORDS + A_WORDS;
            uint4 t;
            t.x=f2tf32(a0v.x); t.y=f2tf32(a0v.y); t.z=f2tf32(a0v.z); t.w=f2tf32(a0v.w);
            *(uint4*)&Ad[ar * A_STRIDE + ac] = t;
            t.x=f2tf32(a1v.x); t.y=f2tf32(a1v.y); t.z=f2tf32(a1v.z); t.w=f2tf32(a1v.w);
            *(uint4*)&Ad[(ar + 64) * A_STRIDE + ac] = t;
            t.x=f2tf32(b0v.x); t.y=f2tf32(b0v.y); t.z=f2tf32(b0v.z); t.w=f2tf32(b0v.w);
            *(uint4*)&Bd[br * B_STRIDE + bc] = t;
            t.x=f2tf32(b1v.x); t.y=f2tf32(b1v.y); t.z=f2tf32(b1v.z); t.w=f2tf32(b1v.w);
            *(uint4*)&Bd[br * B_STRIDE + bc + 64] = t;
            __syncthreads();
            cur ^= 1;
        }
    }

    // epilogue
    #pragma unroll
    for (int mt = 0; mt < 4; mt++) {
        #pragma unroll
        for (int nt = 0; nt < 4; nt++) {
            #pragma unroll
            for (int e = 0; e < 4; e++) {
                int m = m0 + wm * 64 + mt * 16 + l4 + ((e >= 2) ? 8 : 0);
                int n = n0 + wn * 32 + nt * 8 + qq * 2 + (e & 1);
                float val = acc[mt][nt][e];
                if (EPI == 0) {
                    int b_ = m / TT, t_ = m % TT;
                    int head = n >> 6, d = n & 63;
                    C[(((size_t)(b_ * HEADS + head)) * TT + t_) * 64 + d] = val;
                } else if (EPI == 1) {
                    C[(size_t)m * N + n] = val + bias[n] + R[(size_t)m * N + n];
                } else {
                    val += bias[n];
                    C[(size_t)m * N + n] = val > 0.f ? val : 0.f;
                }
            }
        }
    }
}

// ---------------- flash attention: block = (q-tile of 128, b*h), 128 threads ----------------
#define ATTN_SMEM ((64*64 + 64*64 + 128*65) * sizeof(float))

__global__ void __launch_bounds__(128)
attn_kernel(const float* __restrict__ q, const float* __restrict__ k,
            const float* __restrict__ v, float* __restrict__ o) {
    extern __shared__ float sm[];
    float* Ks = sm;            // [64][64]
    float* Vs = sm + 4096;     // [64][64]
    float* Ss = sm + 8192;     // [128][65]

    int bh = blockIdx.y;
    int q0 = blockIdx.x * 128;
    int r  = threadIdx.x;
    int qg = q0 + r;

    const float* qb = q + ((size_t)bh * TT + qg) * 64;
    float qreg[64];
    #pragma unroll
    for (int d = 0; d < 64; d++) qreg[d] = qb[d] * 0.125f;

    float acc[64];
    #pragma unroll
    for (int d = 0; d < 64; d++) acc[d] = 0.f;
    float mrun = -1e30f, lrun = 0.f;

    int kmax = q0 + 128;
    for (int k0 = 0; k0 < kmax; k0 += 64) {
        const float4* kb = (const float4*)(k + ((size_t)bh * TT + k0) * 64);
        const float4* vb = (const float4*)(v + ((size_t)bh * TT + k0) * 64);
        for (int i = r; i < 1024; i += 128) {
            ((float4*)Ks)[i] = kb[i];
            ((float4*)Vs)[i] = vb[i];
        }
        __syncthreads();

        float mx = -1e30f;
        for (int j = 0; j < 64; j++) {
            float s = 0.f;
            const float* kr = Ks + j * 64;
            #pragma unroll
            for (int d = 0; d < 64; d++) s += qreg[d] * kr[d];
            if (k0 + j > qg) s = -1e30f;
            Ss[r * 65 + j] = s;
            mx = fmaxf(mx, s);
        }

        float mnew = fmaxf(mrun, mx);
        float scale = __expf(mrun - mnew);
        lrun *= scale;
        #pragma unroll
        for (int d = 0; d < 64; d++) acc[d] *= scale;
        for (int j = 0; j < 64; j++) {
            float p = __expf(Ss[r * 65 + j] - mnew);
            lrun += p;
            const float* vr = Vs + j * 64;
            #pragma unroll
            for (int d = 0; d < 64; d++) acc[d] += p * vr[d];
        }
        mrun = mnew;
        __syncthreads();
    }

    int b_ = bh / HEADS, h_ = bh % HEADS;
    float* ob = o + ((size_t)(b_ * TT + qg)) * EMB + h_ * 64;
    float inv = 1.f / lrun;
    #pragma unroll
    for (int d = 0; d < 64; d++) ob[d] = acc[d] * inv;
}

// ---------------- launch ----------------
extern "C" void kernel_launch(void* const* d_in, const int* in_sizes, int n_in,
                              void* d_out, int out_size) {
    const float* x   = (const float*)d_in[0];
    const float* Wq  = (const float*)d_in[1];
    const float* Wk  = (const float*)d_in[2];
    const float* Wv  = (const float*)d_in[3];
    const float* Wp  = (const float*)d_in[4];
    const float* bp  = (const float*)d_in[5];
    const float* g1  = (const float*)d_in[6];
    const float* b1  = (const float*)d_in[7];
    const float* g2  = (const float*)d_in[8];
    const float* b2  = (const float*)d_in[9];
    const float* W1  = (const float*)d_in[10];
    const float* bf1 = (const float*)d_in[11];
    const float* W2  = (const float*)d_in[12];
    const float* bf2 = (const float*)d_in[13];
    float* out = (float*)d_out;

    float *h, *q, *k, *v, *o, *h2, *ff;
    cudaGetSymbolAddress((void**)&h,  g_h);
    cudaGetSymbolAddress((void**)&q,  g_q);
    cudaGetSymbolAddress((void**)&k,  g_k);
    cudaGetSymbolAddress((void**)&v,  g_v);
    cudaGetSymbolAddress((void**)&o,  g_o);
    cudaGetSymbolAddress((void**)&h2, g_h2);
    cudaGetSymbolAddress((void**)&ff, g_ff);

    static bool attr_done = false;
    if (!attr_done) {
        cudaFuncSetAttribute(attn_kernel, cudaFuncAttributeMaxDynamicSharedMemorySize,
                             (int)ATTN_SMEM);
        attr_done = true;
    }

    // 1) ln1
    ln_kernel<<<ROWS, 128>>>(x, g1, b1, h);

    // 2) QKV projections (tf32 tensor cores) with head-transposed scatter
    {
        dim3 grid(EMB / 128, ROWS / 128);
        tmma_gemm<0><<<grid, 256, GEMM_SMEM>>>(h, Wq, nullptr, nullptr, q, ROWS, EMB, EMB);
        tmma_gemm<0><<<grid, 256, GEMM_SMEM>>>(h, Wk, nullptr, nullptr, k, ROWS, EMB, EMB);
        tmma_gemm<0><<<grid, 256, GEMM_SMEM>>>(h, Wv, nullptr, nullptr, v, ROWS, EMB, EMB);
    }

    // 3) causal attention
    {
        dim3 grid(TT / 128, BB * HEADS);
        attn_kernel<<<grid, 128, ATTN_SMEM>>>(q, k, v, o);
    }

    // 4) out projection + residual -> d_out
    {
        dim3 grid(EMB / 128, ROWS / 128);
        tmma_gemm<1><<<grid, 256, GEMM_SMEM>>>(o, Wp, bp, x, out, ROWS, EMB, EMB);
    }

    // 5) ln2
    ln_kernel<<<ROWS, 128>>>(out, g2, b2, h2);

    // 6) FF1: relu(h2@W1 + bf1)
    {
        dim3 grid(DFF / 128, ROWS / 128);
        tmma_gemm<2><<<grid, 256, GEMM_SMEM>>>(h2, W1, bf1, nullptr, ff, ROWS, DFF, EMB);
    }

    // 7) FF2: out = x1 + ff@W2 + bf2
    {
        dim3 grid(EMB / 128, ROWS / 128);
        tmma_gemm<1><<<grid, 256, GEMM_SMEM>>>(ff, W2, bf2, out, out, ROWS, EMB, DFF);
    }
}

// round 3
// speedup vs baseline: 3.1999x; 1.4598x over previous
#include <cuda_runtime.h>
#include <math.h>
#include <stdint.h>

#define EMB   384
#define HEADS 6
#define QD    64
#define DFF   1536
#define BB    32
#define TT    512
#define ROWS  (BB*TT)   // 16384

// ---------------- scratch (device globals; no allocation allowed) ----------------
__device__ float g_h [ROWS*EMB];   // ln1 output
__device__ float g_q [ROWS*EMB];   // [B,H,T,D]
__device__ float g_k [ROWS*EMB];
__device__ float g_v [ROWS*EMB];
__device__ float g_o [ROWS*EMB];   // attention output, [B,T,C] layout
__device__ float g_h2[ROWS*EMB];   // ln2 output
__device__ float g_ff[ROWS*DFF];   // relu(h2@W1+b)

// ---------------- LayerNorm: one block per row, 128 threads ----------------
__global__ void ln_kernel(const float* __restrict__ x,
                          const float* __restrict__ g,
                          const float* __restrict__ b,
                          float* __restrict__ out) {
    __shared__ float red[4];
    int row = blockIdx.x;
    int tid = threadIdx.x;
    const float* xr = x + (size_t)row * EMB;

    float v0 = xr[tid], v1 = xr[tid + 128], v2 = xr[tid + 256];
    float s = v0 + v1 + v2;
    #pragma unroll
    for (int o = 16; o; o >>= 1) s += __shfl_xor_sync(0xffffffffu, s, o);
    if ((tid & 31) == 0) red[tid >> 5] = s;
    __syncthreads();
    float mu = (red[0] + red[1] + red[2] + red[3]) * (1.0f / EMB);
    __syncthreads();

    float d0 = v0 - mu, d1 = v1 - mu, d2 = v2 - mu;
    float vv = d0*d0 + d1*d1 + d2*d2;
    #pragma unroll
    for (int o = 16; o; o >>= 1) vv += __shfl_xor_sync(0xffffffffu, vv, o);
    if ((tid & 31) == 0) red[tid >> 5] = vv;
    __syncthreads();
    float var = (red[0] + red[1] + red[2] + red[3]) * (1.0f / EMB);
    float inv = rsqrtf(var + 1e-5f);

    float* orow = out + (size_t)row * EMB;
    orow[tid]       = d0 * inv * g[tid]       + b[tid];
    orow[tid + 128] = d1 * inv * g[tid + 128] + b[tid + 128];
    orow[tid + 256] = d2 * inv * g[tid + 256] + b[tid + 256];
}

// ---------------- TF32 tensor-core GEMM (unchanged from R2) ----------------
#define A_STRIDE 20
#define B_STRIDE 136
#define A_WORDS  (128 * A_STRIDE)
#define B_WORDS  (16  * B_STRIDE)
#define BUF_WORDS (A_WORDS + B_WORDS)
#define GEMM_SMEM (2 * BUF_WORDS * 4)

__device__ __forceinline__ uint32_t f2tf32(float f) {
    uint32_t r;
    asm("cvt.rna.tf32.f32 %0, %1;" : "=r"(r) : "f"(f));
    return r;
}

template<int EPI>
__global__ void __launch_bounds__(256)
tmma_gemm(const float* __restrict__ A, const float* __restrict__ W,
          const float* __restrict__ bias, const float* __restrict__ R,
          float* __restrict__ C, int M, int N, int K) {
    extern __shared__ uint32_t smbuf[];

    int tid  = threadIdx.x;
    int lane = tid & 31;
    int warp = tid >> 5;
    int wm   = warp >> 2;
    int wn   = warp & 3;
    int l4   = lane >> 2;
    int qq   = lane & 3;
    int n0   = blockIdx.x * 128;
    int m0   = blockIdx.y * 128;

    int ar = tid >> 2;
    int ac = (tid & 3) * 4;
    int br = tid >> 4;
    int bc = (tid & 15) * 4;

    float4 a0v, a1v, b0v, b1v;

    float acc[4][4][4];
    #pragma unroll
    for (int mt = 0; mt < 4; mt++)
        #pragma unroll
        for (int nt = 0; nt < 4; nt++)
            #pragma unroll
            for (int e = 0; e < 4; e++) acc[mt][nt][e] = 0.f;

    {
        a0v = *(const float4*)&A[(size_t)(m0 + ar) * K + ac];
        a1v = *(const float4*)&A[(size_t)(m0 + ar + 64) * K + ac];
        b0v = *(const float4*)&W[(size_t)br * N + n0 + bc];
        b1v = *(const float4*)&W[(size_t)br * N + n0 + bc + 64];
        uint32_t* As = smbuf;
        uint32_t* Bs = smbuf + A_WORDS;
        uint4 t;
        t.x=f2tf32(a0v.x); t.y=f2tf32(a0v.y); t.z=f2tf32(a0v.z); t.w=f2tf32(a0v.w);
        *(uint4*)&As[ar * A_STRIDE + ac] = t;
        t.x=f2tf32(a1v.x); t.y=f2tf32(a1v.y); t.z=f2tf32(a1v.z); t.w=f2tf32(a1v.w);
        *(uint4*)&As[(ar + 64) * A_STRIDE + ac] = t;
        t.x=f2tf32(b0v.x); t.y=f2tf32(b0v.y); t.z=f2tf32(b0v.z); t.w=f2tf32(b0v.w);
        *(uint4*)&Bs[br * B_STRIDE + bc] = t;
        t.x=f2tf32(b1v.x); t.y=f2tf32(b1v.y); t.z=f2tf32(b1v.z); t.w=f2tf32(b1v.w);
        *(uint4*)&Bs[br * B_STRIDE + bc + 64] = t;
    }
    __syncthreads();

    int nsteps = K >> 4;
    int cur = 0;
    for (int s = 0; s < nsteps; s++) {
        bool more = (s + 1 < nsteps);
        if (more) {
            int k0 = (s + 1) << 4;
            a0v = *(const float4*)&A[(size_t)(m0 + ar) * K + k0 + ac];
            a1v = *(const float4*)&A[(size_t)(m0 + ar + 64) * K + k0 + ac];
            b0v = *(const float4*)&W[(size_t)(k0 + br) * N + n0 + bc];
            b1v = *(const float4*)&W[(size_t)(k0 + br) * N + n0 + bc + 64];
        }

        uint32_t* As = smbuf + cur * BUF_WORDS;
        uint32_t* Bs = smbuf + cur * BUF_WORDS + A_WORDS;

        #pragma unroll
        for (int kk = 0; kk < 2; kk++) {
            int kb = kk * 8;
            uint32_t af[4][4], bf[4][2];
            #pragma unroll
            for (int mt = 0; mt < 4; mt++) {
                int mrow = wm * 64 + mt * 16 + l4;
                af[mt][0] = As[mrow * A_STRIDE + kb + qq];
                af[mt][1] = As[(mrow + 8) * A_STRIDE + kb + qq];
                af[mt][2] = As[mrow * A_STRIDE + kb + qq + 4];
                af[mt][3] = As[(mrow + 8) * A_STRIDE + kb + qq + 4];
            }
            #pragma unroll
            for (int nt = 0; nt < 4; nt++) {
                int nc = wn * 32 + nt * 8 + l4;
                bf[nt][0] = Bs[(kb + qq) * B_STRIDE + nc];
                bf[nt][1] = Bs[(kb + qq + 4) * B_STRIDE + nc];
            }
            #pragma unroll
            for (int mt = 0; mt < 4; mt++)
                #pragma unroll
                for (int nt = 0; nt < 4; nt++)
                    asm volatile(
                        "mma.sync.aligned.m16n8k8.row.col.f32.tf32.tf32.f32 "
                        "{%0,%1,%2,%3}, {%4,%5,%6,%7}, {%8,%9}, {%0,%1,%2,%3};"
                        : "+f"(acc[mt][nt][0]), "+f"(acc[mt][nt][1]),
                          "+f"(acc[mt][nt][2]), "+f"(acc[mt][nt][3])
                        : "r"(af[mt][0]), "r"(af[mt][1]), "r"(af[mt][2]), "r"(af[mt][3]),
                          "r"(bf[nt][0]), "r"(bf[nt][1]));
        }

        if (more) {
            uint32_t* Ad = smbuf + (cur ^ 1) * BUF_WORDS;
            uint32_t* Bd = smbuf + (cur ^ 1) * BUF_WORDS + A_WORDS;
            uint4 t;
            t.x=f2tf32(a0v.x); t.y=f2tf32(a0v.y); t.z=f2tf32(a0v.z); t.w=f2tf32(a0v.w);
            *(uint4*)&Ad[ar * A_STRIDE + ac] = t;
            t.x=f2tf32(a1v.x); t.y=f2tf32(a1v.y); t.z=f2tf32(a1v.z); t.w=f2tf32(a1v.w);
            *(uint4*)&Ad[(ar + 64) * A_STRIDE + ac] = t;
            t.x=f2tf32(b0v.x); t.y=f2tf32(b0v.y); t.z=f2tf32(b0v.z); t.w=f2tf32(b0v.w);
            *(uint4*)&Bd[br * B_STRIDE + bc] = t;
            t.x=f2tf32(b1v.x); t.y=f2tf32(b1v.y); t.z=f2tf32(b1v.z); t.w=f2tf32(b1v.w);
            *(uint4*)&Bd[br * B_STRIDE + bc + 64] = t;
            __syncthreads();
            cur ^= 1;
        }
    }

    #pragma unroll
    for (int mt = 0; mt < 4; mt++) {
        #pragma unroll
        for (int nt = 0; nt < 4; nt++) {
            #pragma unroll
            for (int e = 0; e < 4; e++) {
                int m = m0 + wm * 64 + mt * 16 + l4 + ((e >= 2) ? 8 : 0);
                int n = n0 + wn * 32 + nt * 8 + qq * 2 + (e & 1);
                float val = acc[mt][nt][e];
                if (EPI == 0) {
                    int b_ = m / TT, t_ = m % TT;
                    int head = n >> 6, d = n & 63;
                    C[(((size_t)(b_ * HEADS + head)) * TT + t_) * 64 + d] = val;
                } else if (EPI == 1) {
                    C[(size_t)m * N + n] = val + bias[n] + R[(size_t)m * N + n];
                } else {
                    val += bias[n];
                    C[(size_t)m * N + n] = val > 0.f ? val : 0.f;
                }
            }
        }
    }
}

// ---------------- tensor-core flash attention ----------------
// Block: 128 queries for one (b,h). 8 warps, each owns a 16-row m-tile.
// Key tiles of 64. S = Q@K^T and O += P@V via mma.m16n8k8 tf32.
// smem word stride 72 everywhere (conflict-free: addr mod 32 = l4*8+qq).
#define ASTR 72
#define AT_Q 0
#define AT_K (128 * ASTR)
#define AT_V (AT_K + 64 * ASTR)
#define AT_P (AT_V + 64 * ASTR)
#define ATTN2_WORDS (AT_P + 128 * ASTR)
#define ATTN2_SMEM (ATTN2_WORDS * 4)

__global__ void __launch_bounds__(256)
attn2_kernel(const float* __restrict__ q, const float* __restrict__ k,
             const float* __restrict__ v, float* __restrict__ o) {
    extern __shared__ uint32_t sm2[];
    uint32_t* Qs = sm2 + AT_Q;
    uint32_t* Ks = sm2 + AT_K;
    uint32_t* Vs = sm2 + AT_V;
    uint32_t* Ps = sm2 + AT_P;

    int tid  = threadIdx.x;
    int lane = tid & 31;
    int warp = tid >> 5;
    int l4   = lane >> 2;
    int qq   = lane & 3;
    int bh   = blockIdx.y;
    int q0   = blockIdx.x * 128;

    // load+convert Q (scaled by 1/8): 128 rows x 16 float4
    {
        const float4* qb = (const float4*)(q + ((size_t)bh * TT + q0) * 64);
        #pragma unroll
        for (int it = 0; it < 8; it++) {
            int i   = tid + it * 256;
            int row = i >> 4, c4 = (i & 15) * 4;
            float4 t = qb[i];
            uint4 u;
            u.x = f2tf32(t.x * 0.125f); u.y = f2tf32(t.y * 0.125f);
            u.z = f2tf32(t.z * 0.125f); u.w = f2tf32(t.w * 0.125f);
            *(uint4*)&Qs[row * ASTR + c4] = u;
        }
    }

    float Oa[8][4];
    #pragma unroll
    for (int nt = 0; nt < 8; nt++)
        #pragma unroll
        for (int e = 0; e < 4; e++) Oa[nt][e] = 0.f;
    float m0 = -1e30f, m1 = -1e30f, l0 = 0.f, l1 = 0.f;

    int mrow  = warp * 16 + l4;           // within tile
    int qg0   = q0 + mrow;                // global query row (e0/e1)
    int qg1   = qg0 + 8;                  // (e2/e3)
    int ktiles = (q0 + 128) >> 6;

    for (int kt = 0; kt < ktiles; kt++) {
        int k0 = kt << 6;
        __syncthreads();   // protect K/V from overwrite until all warps done PV
        {
            const float4* kb = (const float4*)(k + ((size_t)bh * TT + k0) * 64);
            const float4* vb = (const float4*)(v + ((size_t)bh * TT + k0) * 64);
            #pragma unroll
            for (int it = 0; it < 4; it++) {
                int i   = tid + it * 256;
                int row = i >> 4, c4 = (i & 15) * 4;
                float4 t = kb[i];
                uint4 u;
                u.x = f2tf32(t.x); u.y = f2tf32(t.y);
                u.z = f2tf32(t.z); u.w = f2tf32(t.w);
                *(uint4*)&Ks[row * ASTR + c4] = u;
                t = vb[i];
                u.x = f2tf32(t.x); u.y = f2tf32(t.y);
                u.z = f2tf32(t.z); u.w = f2tf32(t.w);
                *(uint4*)&Vs[row * ASTR + c4] = u;
            }
        }
        __syncthreads();

        // ---- S = Q @ K^T : 8 n-tiles x 8 k-steps ----
        float s[8][4];
        #pragma unroll
        for (int nt = 0; nt < 8; nt++)
            #pragma unroll
            for (int e = 0; e < 4; e++) s[nt][e] = 0.f;

        #pragma unroll
        for (int kk = 0; kk < 8; kk++) {
            int kb = kk * 8;
            uint32_t af[4];
            af[0] = Qs[mrow * ASTR + kb + qq];
            af[1] = Qs[(mrow + 8) * ASTR + kb + qq];
            af[2] = Qs[mrow * ASTR + kb + qq + 4];
            af[3] = Qs[(mrow + 8) * ASTR + kb + qq + 4];
            #pragma unroll
            for (int nt = 0; nt < 8; nt++) {
                uint32_t b0 = Ks[(nt * 8 + l4) * ASTR + kb + qq];
                uint32_t b1 = Ks[(nt * 8 + l4) * ASTR + kb + qq + 4];
                asm volatile(
                    "mma.sync.aligned.m16n8k8.row.col.f32.tf32.tf32.f32 "
                    "{%0,%1,%2,%3}, {%4,%5,%6,%7}, {%8,%9}, {%0,%1,%2,%3};"
                    : "+f"(s[nt][0]), "+f"(s[nt][1]), "+f"(s[nt][2]), "+f"(s[nt][3])
                    : "r"(af[0]), "r"(af[1]), "r"(af[2]), "r"(af[3]),
                      "r"(b0), "r"(b1));
            }
        }

        // ---- causal mask (only diagonal region matters; cheap enough always) ----
        if (k0 + 63 > qg0) {
            #pragma unroll
            for (int nt = 0; nt < 8; nt++) {
                int kg = k0 + nt * 8 + 2 * qq;
                if (kg     > qg0) s[nt][0] = -1e30f;
                if (kg + 1 > qg0) s[nt][1] = -1e30f;
                if (kg     > qg1) s[nt][2] = -1e30f;
                if (kg + 1 > qg1) s[nt][3] = -1e30f;
            }
        }

        // ---- online softmax in fragments ----
        float r0 = -1e30f, r1 = -1e30f;
        #pragma unroll
        for (int nt = 0; nt < 8; nt++) {
            r0 = fmaxf(r0, fmaxf(s[nt][0], s[nt][1]));
            r1 = fmaxf(r1, fmaxf(s[nt][2], s[nt][3]));
        }
        r0 = fmaxf(r0, __shfl_xor_sync(0xffffffffu, r0, 1));
        r0 = fmaxf(r0, __shfl_xor_sync(0xffffffffu, r0, 2));
        r1 = fmaxf(r1, __shfl_xor_sync(0xffffffffu, r1, 1));
        r1 = fmaxf(r1, __shfl_xor_sync(0xffffffffu, r1, 2));

        float mn0 = fmaxf(m0, r0), mn1 = fmaxf(m1, r1);
        float sc0 = __expf(m0 - mn0), sc1 = __expf(m1 - mn1);
        float rs0 = 0.f, rs1 = 0.f;
        #pragma unroll
        for (int nt = 0; nt < 8; nt++) {
            s[nt][0] = __expf(s[nt][0] - mn0);
            s[nt][1] = __expf(s[nt][1] - mn0);
            s[nt][2] = __expf(s[nt][2] - mn1);
            s[nt][3] = __expf(s[nt][3] - mn1);
            rs0 += s[nt][0] + s[nt][1];
            rs1 += s[nt][2] + s[nt][3];
        }
        rs0 += __shfl_xor_sync(0xffffffffu, rs0, 1);
        rs0 += __shfl_xor_sync(0xffffffffu, rs0, 2);
        rs1 += __shfl_xor_sync(0xffffffffu, rs1, 1);
        rs1 += __shfl_xor_sync(0xffffffffu, rs1, 2);
        l0 = l0 * sc0 + rs0;
        l1 = l1 * sc1 + rs1;
        m0 = mn0; m1 = mn1;

        #pragma unroll
        for (int nt = 0; nt < 8; nt++) {
            Oa[nt][0] *= sc0; Oa[nt][1] *= sc0;
            Oa[nt][2] *= sc1; Oa[nt][3] *= sc1;
        }

        // ---- store P to warp-private smem rows (tf32) ----
        #pragma unroll
        for (int nt = 0; nt < 8; nt++) {
            uint2 u;
            u.x = f2tf32(s[nt][0]); u.y = f2tf32(s[nt][1]);
            *(uint2*)&Ps[mrow * ASTR + nt * 8 + 2 * qq] = u;
            u.x = f2tf32(s[nt][2]); u.y = f2tf32(s[nt][3]);
            *(uint2*)&Ps[(mrow + 8) * ASTR + nt * 8 + 2 * qq] = u;
        }
        __syncwarp();

        // ---- O += P @ V : k over 64 keys, n over 64 dims ----
        #pragma unroll
        for (int kk = 0; kk < 8; kk++) {
            int kb = kk * 8;
            uint32_t af[4];
            af[0] = Ps[mrow * ASTR + kb + qq];
            af[1] = Ps[(mrow + 8) * ASTR + kb + qq];
            af[2] = Ps[mrow * ASTR + kb + qq + 4];
            af[3] = Ps[(mrow + 8) * ASTR + kb + qq + 4];
            #pragma unroll
            for (int nt = 0; nt < 8; nt++) {
                uint32_t b0 = Vs[(kb + qq) * ASTR + nt * 8 + l4];
                uint32_t b1 = Vs[(kb + qq + 4) * ASTR + nt * 8 + l4];
                asm volatile(
                    "mma.sync.aligned.m16n8k8.row.col.f32.tf32.tf32.f32 "
                    "{%0,%1,%2,%3}, {%4,%5,%6,%7}, {%8,%9}, {%0,%1,%2,%3};"
                    : "+f"(Oa[nt][0]), "+f"(Oa[nt][1]), "+f"(Oa[nt][2]), "+f"(Oa[nt][3])
                    : "r"(af[0]), "r"(af[1]), "r"(af[2]), "r"(af[3]),
                      "r"(b0), "r"(b1));
            }
        }
    }

    // ---- epilogue: normalize and write [B,T,C] ----
    int b_ = bh / HEADS, h_ = bh % HEADS;
    float inv0 = 1.f / l0, inv1 = 1.f / l1;
    float* ob0 = o + ((size_t)(b_ * TT + qg0)) * EMB + h_ * 64;
    float* ob1 = o + ((size_t)(b_ * TT + qg1)) * EMB + h_ * 64;
    #pragma unroll
    for (int nt = 0; nt < 8; nt++) {
        float2 t0 = make_float2(Oa[nt][0] * inv0, Oa[nt][1] * inv0);
        float2 t1 = make_float2(Oa[nt][2] * inv1, Oa[nt][3] * inv1);
        *(float2*)&ob0[nt * 8 + 2 * qq] = t0;
        *(float2*)&ob1[nt * 8 + 2 * qq] = t1;
    }
}

// ---------------- launch ----------------
extern "C" void kernel_launch(void* const* d_in, const int* in_sizes, int n_in,
                              void* d_out, int out_size) {
    const float* x   = (const float*)d_in[0];
    const float* Wq  = (const float*)d_in[1];
    const float* Wk  = (const float*)d_in[2];
    const float* Wv  = (const float*)d_in[3];
    const float* Wp  = (const float*)d_in[4];
    const float* bp  = (const float*)d_in[5];
    const float* g1  = (const float*)d_in[6];
    const float* b1  = (const float*)d_in[7];
    const float* g2  = (const float*)d_in[8];
    const float* b2  = (const float*)d_in[9];
    const float* W1  = (const float*)d_in[10];
    const float* bf1 = (const float*)d_in[11];
    const float* W2  = (const float*)d_in[12];
    const float* bf2 = (const float*)d_in[13];
    float* out = (float*)d_out;

    float *h, *q, *k, *v, *o, *h2, *ff;
    cudaGetSymbolAddress((void**)&h,  g_h);
    cudaGetSymbolAddress((void**)&q,  g_q);
    cudaGetSymbolAddress((void**)&k,  g_k);
    cudaGetSymbolAddress((void**)&v,  g_v);
    cudaGetSymbolAddress((void**)&o,  g_o);
    cudaGetSymbolAddress((void**)&h2, g_h2);
    cudaGetSymbolAddress((void**)&ff, g_ff);

    static bool attr_done = false;
    if (!attr_done) {
        cudaFuncSetAttribute(attn2_kernel, cudaFuncAttributeMaxDynamicSharedMemorySize,
                             (int)ATTN2_SMEM);
        attr_done = true;
    }

    // 1) ln1
    ln_kernel<<<ROWS, 128>>>(x, g1, b1, h);

    // 2) QKV projections
    {
        dim3 grid(EMB / 128, ROWS / 128);
        tmma_gemm<0><<<grid, 256, GEMM_SMEM>>>(h, Wq, nullptr, nullptr, q, ROWS, EMB, EMB);
        tmma_gemm<0><<<grid, 256, GEMM_SMEM>>>(h, Wk, nullptr, nullptr, k, ROWS, EMB, EMB);
        tmma_gemm<0><<<grid, 256, GEMM_SMEM>>>(h, Wv, nullptr, nullptr, v, ROWS, EMB, EMB);
    }

    // 3) causal attention (tensor cores)
    {
        dim3 grid(TT / 128, BB * HEADS);
        attn2_kernel<<<grid, 256, ATTN2_SMEM>>>(q, k, v, o);
    }

    // 4) out projection + residual -> d_out
    {
        dim3 grid(EMB / 128, ROWS / 128);
        tmma_gemm<1><<<grid, 256, GEMM_SMEM>>>(o, Wp, bp, x, out, ROWS, EMB, EMB);
    }

    // 5) ln2
    ln_kernel<<<ROWS, 128>>>(out, g2, b2, h2);

    // 6) FF1
    {
        dim3 grid(DFF / 128, ROWS / 128);
        tmma_gemm<2><<<grid, 256, GEMM_SMEM>>>(h2, W1, bf1, nullptr, ff, ROWS, DFF, EMB);
    }

    // 7) FF2
    {
        dim3 grid(EMB / 128, ROWS / 128);
        tmma_gemm<1><<<grid, 256, GEMM_SMEM>>>(ff, W2, bf2, out, out, ROWS, EMB, DFF);
    }
}

// round 4
// speedup vs baseline: 3.5054x; 1.0955x over previous
#include <cuda_runtime.h>
#include <math.h>
#include <stdint.h>

#define EMB   384
#define HEADS 6
#define QD    64
#define DFF   1536
#define BB    32
#define TT    512
#define ROWS  (BB*TT)   // 16384

// ---------------- scratch (device globals; no allocation allowed) ----------------
__device__ float g_h [ROWS*EMB];   // ln1 output
__device__ float g_q [ROWS*EMB];   // [B,H,T,D]
__device__ float g_k [ROWS*EMB];
__device__ float g_v [ROWS*EMB];
__device__ float g_o [ROWS*EMB];   // attention output, [B,T,C] layout
__device__ float g_h2[ROWS*EMB];   // ln2 output
__device__ float g_ff[ROWS*DFF];   // relu(h2@W1+b)

// ---------------- LayerNorm: one block per row, 128 threads ----------------
__global__ void ln_kernel(const float* __restrict__ x,
                          const float* __restrict__ g,
                          const float* __restrict__ b,
                          float* __restrict__ out) {
    __shared__ float red[4];
    int row = blockIdx.x;
    int tid = threadIdx.x;
    const float* xr = x + (size_t)row * EMB;

    float v0 = xr[tid], v1 = xr[tid + 128], v2 = xr[tid + 256];
    float s = v0 + v1 + v2;
    #pragma unroll
    for (int o = 16; o; o >>= 1) s += __shfl_xor_sync(0xffffffffu, s, o);
    if ((tid & 31) == 0) red[tid >> 5] = s;
    __syncthreads();
    float mu = (red[0] + red[1] + red[2] + red[3]) * (1.0f / EMB);
    __syncthreads();

    float d0 = v0 - mu, d1 = v1 - mu, d2 = v2 - mu;
    float vv = d0*d0 + d1*d1 + d2*d2;
    #pragma unroll
    for (int o = 16; o; o >>= 1) vv += __shfl_xor_sync(0xffffffffu, vv, o);
    if ((tid & 31) == 0) red[tid >> 5] = vv;
    __syncthreads();
    float var = (red[0] + red[1] + red[2] + red[3]) * (1.0f / EMB);
    float inv = rsqrtf(var + 1e-5f);

    float* orow = out + (size_t)row * EMB;
    orow[tid]       = d0 * inv * g[tid]       + b[tid];
    orow[tid + 128] = d1 * inv * g[tid + 128] + b[tid + 128];
    orow[tid + 256] = d2 * inv * g[tid + 256] + b[tid + 256];
}

// ---------------- TF32 tensor GEMM, 3-stage cp.async pipeline ----------------
// BM=BN=128, BK=16, 256 threads (2x4 warps), warp tile 64x32.
// Raw fp32 fed to mma.tf32 (hardware RZ truncation). A stride 20, B stride 136.
#define A_STRIDE 20
#define B_STRIDE 136
#define A_WORDS  (128 * A_STRIDE)          // 2560
#define B_WORDS  (16  * B_STRIDE)          // 2176
#define BUF_WORDS (A_WORDS + B_WORDS)      // 4736
#define BUF_BYTES (BUF_WORDS * 4)          // 18944
#define GEMM_SMEM (3 * BUF_BYTES)          // 56832

__device__ __forceinline__ uint32_t f2tf32(float f) {
    uint32_t r;
    asm("cvt.rna.tf32.f32 %0, %1;" : "=r"(r) : "f"(f));
    return r;
}

__device__ __forceinline__ void cp16(uint32_t saddr, const void* gptr) {
    asm volatile("cp.async.cg.shared.global [%0], [%1], 16;"
                 :: "r"(saddr), "l"(gptr));
}

template<int EPI>
__global__ void __launch_bounds__(256)
tmma_gemm(const float* __restrict__ A, const float* __restrict__ W,
          const float* __restrict__ bias, const float* __restrict__ R,
          float* __restrict__ C, int M, int N, int K) {
    extern __shared__ uint32_t smbuf[];
    uint32_t sbase = (uint32_t)__cvta_generic_to_shared(smbuf);

    int tid  = threadIdx.x;
    int lane = tid & 31;
    int warp = tid >> 5;
    int wm   = warp >> 2;
    int wn   = warp & 3;
    int l4   = lane >> 2;
    int qq   = lane & 3;
    int n0   = blockIdx.x * 128;
    int m0   = blockIdx.y * 128;

    int ar = tid >> 2;           // 0..63
    int ac = (tid & 3) * 4;      // 0,4,8,12
    int br = tid >> 4;           // 0..15
    int bc = (tid & 15) * 4;     // 0..60

    const float* Ap0 = &A[(size_t)(m0 + ar) * K + ac];
    const float* Ap1 = &A[(size_t)(m0 + ar + 64) * K + ac];
    const float* Bp0 = &W[(size_t)br * N + n0 + bc];
    const float* Bp1 = Bp0 + 64;

    uint32_t sA0 = sbase + (ar * A_STRIDE + ac) * 4;
    uint32_t sA1 = sbase + ((ar + 64) * A_STRIDE + ac) * 4;
    uint32_t sB0 = sbase + (A_WORDS + br * B_STRIDE + bc) * 4;
    uint32_t sB1 = sB0 + 64 * 4;

    float acc[4][4][4];
    #pragma unroll
    for (int mt = 0; mt < 4; mt++)
        #pragma unroll
        for (int nt = 0; nt < 4; nt++)
            #pragma unroll
            for (int e = 0; e < 4; e++) acc[mt][nt][e] = 0.f;

    int nsteps = K >> 4;

    // prologue: issue stages 0 and 1
    #pragma unroll
    for (int s = 0; s < 2; s++) {
        uint32_t off = s * BUF_BYTES;
        cp16(sA0 + off, Ap0 + (s << 4));
        cp16(sA1 + off, Ap1 + (s << 4));
        cp16(sB0 + off, Bp0 + (size_t)(s << 4) * N);
        cp16(sB1 + off, Bp1 + (size_t)(s << 4) * N);
        asm volatile("cp.async.commit_group;");
    }
    asm volatile("cp.async.wait_group 1;");
    __syncthreads();

    int cur = 0;
    for (int s = 0; s < nsteps; s++) {
        uint32_t* As = smbuf + cur * BUF_WORDS;
        uint32_t* Bs = smbuf + cur * BUF_WORDS + A_WORDS;

        #pragma unroll
        for (int kk = 0; kk < 2; kk++) {
            int kb = kk * 8;
            uint32_t af[4][4], bf[4][2];
            #pragma unroll
            for (int mt = 0; mt < 4; mt++) {
                int mrow = wm * 64 + mt * 16 + l4;
                af[mt][0] = As[mrow * A_STRIDE + kb + qq];
                af[mt][1] = As[(mrow + 8) * A_STRIDE + kb + qq];
                af[mt][2] = As[mrow * A_STRIDE + kb + qq + 4];
                af[mt][3] = As[(mrow + 8) * A_STRIDE + kb + qq + 4];
            }
            #pragma unroll
            for (int nt = 0; nt < 4; nt++) {
                int nc = wn * 32 + nt * 8 + l4;
                bf[nt][0] = Bs[(kb + qq) * B_STRIDE + nc];
                bf[nt][1] = Bs[(kb + qq + 4) * B_STRIDE + nc];
            }
            #pragma unroll
            for (int mt = 0; mt < 4; mt++)
                #pragma unroll
                for (int nt = 0; nt < 4; nt++)
                    asm volatile(
                        "mma.sync.aligned.m16n8k8.row.col.f32.tf32.tf32.f32 "
                        "{%0,%1,%2,%3}, {%4,%5,%6,%7}, {%8,%9}, {%0,%1,%2,%3};"
                        : "+f"(acc[mt][nt][0]), "+f"(acc[mt][nt][1]),
                          "+f"(acc[mt][nt][2]), "+f"(acc[mt][nt][3])
                        : "r"(af[mt][0]), "r"(af[mt][1]), "r"(af[mt][2]), "r"(af[mt][3]),
                          "r"(bf[nt][0]), "r"(bf[nt][1]));
        }

        int nx = s + 2;
        if (nx < nsteps) {
            uint32_t off = (uint32_t)(nx % 3) * BUF_BYTES;
            cp16(sA0 + off, Ap0 + (nx << 4));
            cp16(sA1 + off, Ap1 + (nx << 4));
            cp16(sB0 + off, Bp0 + (size_t)(nx << 4) * N);
            cp16(sB1 + off, Bp1 + (size_t)(nx << 4) * N);
            asm volatile("cp.async.commit_group;");
            asm volatile("cp.async.wait_group 1;");
        } else {
            asm volatile("cp.async.wait_group 0;");
        }
        __syncthreads();
        cur = (cur + 1) % 3;
    }

    // epilogue
    #pragma unroll
    for (int mt = 0; mt < 4; mt++) {
        #pragma unroll
        for (int nt = 0; nt < 4; nt++) {
            #pragma unroll
            for (int e = 0; e < 4; e++) {
                int m = m0 + wm * 64 + mt * 16 + l4 + ((e >= 2) ? 8 : 0);
                int n = n0 + wn * 32 + nt * 8 + qq * 2 + (e & 1);
                float val = acc[mt][nt][e];
                if (EPI == 0) {
                    int b_ = m >> 9, t_ = m & 511;   // TT=512
                    int head = n >> 6, d = n & 63;
                    C[(((size_t)(b_ * HEADS + head)) * TT + t_) * 64 + d] = val;
                } else if (EPI == 1) {
                    C[(size_t)m * N + n] = val + bias[n] + R[(size_t)m * N + n];
                } else {
                    val += bias[n];
                    C[(size_t)m * N + n] = val > 0.f ? val : 0.f;
                }
            }
        }
    }
}

// ---------------- tensor-core flash attention (unchanged from R3) ----------------
#define ASTR 72
#define AT_Q 0
#define AT_K (128 * ASTR)
#define AT_V (AT_K + 64 * ASTR)
#define AT_P (AT_V + 64 * ASTR)
#define ATTN2_WORDS (AT_P + 128 * ASTR)
#define ATTN2_SMEM (ATTN2_WORDS * 4)

__global__ void __launch_bounds__(256)
attn2_kernel(const float* __restrict__ q, const float* __restrict__ k,
             const float* __restrict__ v, float* __restrict__ o) {
    extern __shared__ uint32_t sm2[];
    uint32_t* Qs = sm2 + AT_Q;
    uint32_t* Ks = sm2 + AT_K;
    uint32_t* Vs = sm2 + AT_V;
    uint32_t* Ps = sm2 + AT_P;

    int tid  = threadIdx.x;
    int lane = tid & 31;
    int warp = tid >> 5;
    int l4   = lane >> 2;
    int qq   = lane & 3;
    int bh   = blockIdx.y;
    int q0   = blockIdx.x * 128;

    {
        const float4* qb = (const float4*)(q + ((size_t)bh * TT + q0) * 64);
        #pragma unroll
        for (int it = 0; it < 8; it++) {
            int i   = tid + it * 256;
            int row = i >> 4, c4 = (i & 15) * 4;
            float4 t = qb[i];
            uint4 u;
            u.x = f2tf32(t.x * 0.125f); u.y = f2tf32(t.y * 0.125f);
            u.z = f2tf32(t.z * 0.125f); u.w = f2tf32(t.w * 0.125f);
            *(uint4*)&Qs[row * ASTR + c4] = u;
        }
    }

    float Oa[8][4];
    #pragma unroll
    for (int nt = 0; nt < 8; nt++)
        #pragma unroll
        for (int e = 0; e < 4; e++) Oa[nt][e] = 0.f;
    float m0 = -1e30f, m1 = -1e30f, l0 = 0.f, l1 = 0.f;

    int mrow  = warp * 16 + l4;
    int qg0   = q0 + mrow;
    int qg1   = qg0 + 8;
    int ktiles = (q0 + 128) >> 6;

    for (int kt = 0; kt < ktiles; kt++) {
        int k0 = kt << 6;
        __syncthreads();
        {
            const float4* kb = (const float4*)(k + ((size_t)bh * TT + k0) * 64);
            const float4* vb = (const float4*)(v + ((size_t)bh * TT + k0) * 64);
            #pragma unroll
            for (int it = 0; it < 4; it++) {
                int i   = tid + it * 256;
                int row = i >> 4, c4 = (i & 15) * 4;
                float4 t = kb[i];
                uint4 u;
                u.x = f2tf32(t.x); u.y = f2tf32(t.y);
                u.z = f2tf32(t.z); u.w = f2tf32(t.w);
                *(uint4*)&Ks[row * ASTR + c4] = u;
                t = vb[i];
                u.x = f2tf32(t.x); u.y = f2tf32(t.y);
                u.z = f2tf32(t.z); u.w = f2tf32(t.w);
                *(uint4*)&Vs[row * ASTR + c4] = u;
            }
        }
        __syncthreads();

        float s[8][4];
        #pragma unroll
        for (int nt = 0; nt < 8; nt++)
            #pragma unroll
            for (int e = 0; e < 4; e++) s[nt][e] = 0.f;

        #pragma unroll
        for (int kk = 0; kk < 8; kk++) {
            int kb = kk * 8;
            uint32_t af[4];
            af[0] = Qs[mrow * ASTR + kb + qq];
            af[1] = Qs[(mrow + 8) * ASTR + kb + qq];
            af[2] = Qs[mrow * ASTR + kb + qq + 4];
            af[3] = Qs[(mrow + 8) * ASTR + kb + qq + 4];
            #pragma unroll
            for (int nt = 0; nt < 8; nt++) {
                uint32_t b0 = Ks[(nt * 8 + l4) * ASTR + kb + qq];
                uint32_t b1 = Ks[(nt * 8 + l4) * ASTR + kb + qq + 4];
                asm volatile(
                    "mma.sync.aligned.m16n8k8.row.col.f32.tf32.tf32.f32 "
                    "{%0,%1,%2,%3}, {%4,%5,%6,%7}, {%8,%9}, {%0,%1,%2,%3};"
                    : "+f"(s[nt][0]), "+f"(s[nt][1]), "+f"(s[nt][2]), "+f"(s[nt][3])
                    : "r"(af[0]), "r"(af[1]), "r"(af[2]), "r"(af[3]),
                      "r"(b0), "r"(b1));
            }
        }

        if (k0 + 63 > qg0) {
            #pragma unroll
            for (int nt = 0; nt < 8; nt++) {
                int kg = k0 + nt * 8 + 2 * qq;
                if (kg     > qg0) s[nt][0] = -1e30f;
                if (kg + 1 > qg0) s[nt][1] = -1e30f;
                if (kg     > qg1) s[nt][2] = -1e30f;
                if (kg + 1 > qg1) s[nt][3] = -1e30f;
            }
        }

        float r0 = -1e30f, r1 = -1e30f;
        #pragma unroll
        for (int nt = 0; nt < 8; nt++) {
            r0 = fmaxf(r0, fmaxf(s[nt][0], s[nt][1]));
            r1 = fmaxf(r1, fmaxf(s[nt][2], s[nt][3]));
        }
        r0 = fmaxf(r0, __shfl_xor_sync(0xffffffffu, r0, 1));
        r0 = fmaxf(r0, __shfl_xor_sync(0xffffffffu, r0, 2));
        r1 = fmaxf(r1, __shfl_xor_sync(0xffffffffu, r1, 1));
        r1 = fmaxf(r1, __shfl_xor_sync(0xffffffffu, r1, 2));

        float mn0 = fmaxf(m0, r0), mn1 = fmaxf(m1, r1);
        float sc0 = __expf(m0 - mn0), sc1 = __expf(m1 - mn1);
        float rs0 = 0.f, rs1 = 0.f;
        #pragma unroll
        for (int nt = 0; nt < 8; nt++) {
            s[nt][0] = __expf(s[nt][0] - mn0);
            s[nt][1] = __expf(s[nt][1] - mn0);
            s[nt][2] = __expf(s[nt][2] - mn1);
            s[nt][3] = __expf(s[nt][3] - mn1);
            rs0 += s[nt][0] + s[nt][1];
            rs1 += s[nt][2] + s[nt][3];
        }
        rs0 += __shfl_xor_sync(0xffffffffu, rs0, 1);
        rs0 += __shfl_xor_sync(0xffffffffu, rs0, 2);
        rs1 += __shfl_xor_sync(0xffffffffu, rs1, 1);
        rs1 += __shfl_xor_sync(0xffffffffu, rs1, 2);
        l0 = l0 * sc0 + rs0;
        l1 = l1 * sc1 + rs1;
        m0 = mn0; m1 = mn1;

        #pragma unroll
        for (int nt = 0; nt < 8; nt++) {
            Oa[nt][0] *= sc0; Oa[nt][1] *= sc0;
            Oa[nt][2] *= sc1; Oa[nt][3] *= sc1;
        }

        #pragma unroll
        for (int nt = 0; nt < 8; nt++) {
            uint2 u;
            u.x = f2tf32(s[nt][0]); u.y = f2tf32(s[nt][1]);
            *(uint2*)&Ps[mrow * ASTR + nt * 8 + 2 * qq] = u;
            u.x = f2tf32(s[nt][2]); u.y = f2tf32(s[nt][3]);
            *(uint2*)&Ps[(mrow + 8) * ASTR + nt * 8 + 2 * qq] = u;
        }
        __syncwarp();

        #pragma unroll
        for (int kk = 0; kk < 8; kk++) {
            int kb = kk * 8;
            uint32_t af[4];
            af[0] = Ps[mrow * ASTR + kb + qq];
            af[1] = Ps[(mrow + 8) * ASTR + kb + qq];
            af[2] = Ps[mrow * ASTR + kb + qq + 4];
            af[3] = Ps[(mrow + 8) * ASTR + kb + qq + 4];
            #pragma unroll
            for (int nt = 0; nt < 8; nt++) {
                uint32_t b0 = Vs[(kb + qq) * ASTR + nt * 8 + l4];
                uint32_t b1 = Vs[(kb + qq + 4) * ASTR + nt * 8 + l4];
                asm volatile(
                    "mma.sync.aligned.m16n8k8.row.col.f32.tf32.tf32.f32 "
                    "{%0,%1,%2,%3}, {%4,%5,%6,%7}, {%8,%9}, {%0,%1,%2,%3};"
                    : "+f"(Oa[nt][0]), "+f"(Oa[nt][1]), "+f"(Oa[nt][2]), "+f"(Oa[nt][3])
                    : "r"(af[0]), "r"(af[1]), "r"(af[2]), "r"(af[3]),
                      "r"(b0), "r"(b1));
            }
        }
    }

    int b_ = bh / HEADS, h_ = bh % HEADS;
    float inv0 = 1.f / l0, inv1 = 1.f / l1;
    float* ob0 = o + ((size_t)(b_ * TT + qg0)) * EMB + h_ * 64;
    float* ob1 = o + ((size_t)(b_ * TT + qg1)) * EMB + h_ * 64;
    #pragma unroll
    for (int nt = 0; nt < 8; nt++) {
        float2 t0 = make_float2(Oa[nt][0] * inv0, Oa[nt][1] * inv0);
        float2 t1 = make_float2(Oa[nt][2] * inv1, Oa[nt][3] * inv1);
        *(float2*)&ob0[nt * 8 + 2 * qq] = t0;
        *(float2*)&ob1[nt * 8 + 2 * qq] = t1;
    }
}

// ---------------- launch ----------------
extern "C" void kernel_launch(void* const* d_in, const int* in_sizes, int n_in,
                              void* d_out, int out_size) {
    const float* x   = (const float*)d_in[0];
    const float* Wq  = (const float*)d_in[1];
    const float* Wk  = (const float*)d_in[2];
    const float* Wv  = (const float*)d_in[3];
    const float* Wp  = (const float*)d_in[4];
    const float* bp  = (const float*)d_in[5];
    const float* g1  = (const float*)d_in[6];
    const float* b1  = (const float*)d_in[7];
    const float* g2  = (const float*)d_in[8];
    const float* b2  = (const float*)d_in[9];
    const float* W1  = (const float*)d_in[10];
    const float* bf1 = (const float*)d_in[11];
    const float* W2  = (const float*)d_in[12];
    const float* bf2 = (const float*)d_in[13];
    float* out = (float*)d_out;

    float *h, *q, *k, *v, *o, *h2, *ff;
    cudaGetSymbolAddress((void**)&h,  g_h);
    cudaGetSymbolAddress((void**)&q,  g_q);
    cudaGetSymbolAddress((void**)&k,  g_k);
    cudaGetSymbolAddress((void**)&v,  g_v);
    cudaGetSymbolAddress((void**)&o,  g_o);
    cudaGetSymbolAddress((void**)&h2, g_h2);
    cudaGetSymbolAddress((void**)&ff, g_ff);

    static bool attr_done = false;
    if (!attr_done) {
        cudaFuncSetAttribute(attn2_kernel, cudaFuncAttributeMaxDynamicSharedMemorySize,
                             (int)ATTN2_SMEM);
        cudaFuncSetAttribute(tmma_gemm<0>, cudaFuncAttributeMaxDynamicSharedMemorySize,
                             (int)GEMM_SMEM);
        cudaFuncSetAttribute(tmma_gemm<1>, cudaFuncAttributeMaxDynamicSharedMemorySize,
                             (int)GEMM_SMEM);
        cudaFuncSetAttribute(tmma_gemm<2>, cudaFuncAttributeMaxDynamicSharedMemorySize,
                             (int)GEMM_SMEM);
        attr_done = true;
    }

    // 1) ln1
    ln_kernel<<<ROWS, 128>>>(x, g1, b1, h);

    // 2) QKV projections
    {
        dim3 grid(EMB / 128, ROWS / 128);
        tmma_gemm<0><<<grid, 256, GEMM_SMEM>>>(h, Wq, nullptr, nullptr, q, ROWS, EMB, EMB);
        tmma_gemm<0><<<grid, 256, GEMM_SMEM>>>(h, Wk, nullptr, nullptr, k, ROWS, EMB, EMB);
        tmma_gemm<0><<<grid, 256, GEMM_SMEM>>>(h, Wv, nullptr, nullptr, v, ROWS, EMB, EMB);
    }

    // 3) causal attention
    {
        dim3 grid(TT / 128, BB * HEADS);
        attn2_kernel<<<grid, 256, ATTN2_SMEM>>>(q, k, v, o);
    }

    // 4) out projection + residual -> d_out
    {
        dim3 grid(EMB / 128, ROWS / 128);
        tmma_gemm<1><<<grid, 256, GEMM_SMEM>>>(o, Wp, bp, x, out, ROWS, EMB, EMB);
    }

    // 5) ln2
    ln_kernel<<<ROWS, 128>>>(out, g2, b2, h2);

    // 6) FF1
    {
        dim3 grid(DFF / 128, ROWS / 128);
        tmma_gemm<2><<<grid, 256, GEMM_SMEM>>>(h2, W1, bf1, nullptr, ff, ROWS, DFF, EMB);
    }

    // 7) FF2
    {
        dim3 grid(EMB / 128, ROWS / 128);
        tmma_gemm<1><<<grid, 256, GEMM_SMEM>>>(ff, W2, bf2, out, out, ROWS, EMB, DFF);
    }
}